// round 6
// baseline (speedup 1.0000x reference)
#include <cuda_runtime.h>
#include <cuda_bf16.h>

#define N_CLASSES 9
#define N_GROUPS  2
#define N_BINS    (N_CLASSES * N_GROUPS)   // 18
#define THREADS_PER_BLOCK 256
#define CTAS_PER_SM 4
#define NUM_SMS 148
#define CHUNK_I4 1024                      // int4 per chunk (4096 elements)

// Global scratch (no allocations). Zero-initialized at load; the last block of
// every launch resets everything, so each graph replay sees clean state.
__device__ unsigned int g_counts[N_BINS];
__device__ unsigned int g_work;
__device__ unsigned int g_ticket;

// Packed accumulate: 9 class-fields x 7 bits in a 64-bit register, one
// accumulator per attr value. ~9 SASS instrs/element, IMAD on fma pipe.
__device__ __forceinline__ void acc_elem(int pred, int attr,
                                         unsigned long long& acc0,
                                         unsigned long long& acc1)
{
    unsigned s = (unsigned)pred * 7u;
    unsigned long long inc = 1ULL << s;
    if (attr) acc1 += inc; else acc0 += inc;   // predicated IADD3/IADD3.X
}

__device__ __forceinline__ void flush_pair(unsigned long long& acc0,
                                           unsigned long long& acc1,
                                           unsigned int* blk)
{
    #pragma unroll
    for (int c = 0; c < N_CLASSES; c++) {
        unsigned f0 = (unsigned)(acc0 >> (7 * c)) & 0x7Fu;
        unsigned f1 = (unsigned)(acc1 >> (7 * c)) & 0x7Fu;
        atomicAdd(&blk[2 * c + 0], f0);   // warp-uniform -> REDUX-aggregated
        atomicAdd(&blk[2 * c + 1], f1);
    }
    acc0 = 0ULL;
    acc1 = 0ULL;
}

__global__ void __launch_bounds__(THREADS_PER_BLOCK, CTAS_PER_SM)
spd_loss_kernel(const int* __restrict__ preds,
                const int* __restrict__ attrs,
                float* __restrict__ out,
                int n, int n4, float n_total)
{
    __shared__ unsigned int blk[N_BINS];
    __shared__ unsigned int s_chunk[2];   // double-buffered ticket broadcast
    __shared__ unsigned int is_last;

    if (threadIdx.x < N_BINS) blk[threadIdx.x] = 0u;

    // Two independent accumulator pairs (half-length dependency chains).
    unsigned long long a0 = 0ULL, a1 = 0ULL;
    unsigned long long b0 = 0ULL, b1 = 0ULL;

    const int4* __restrict__ p4 = (const int4*)preds;
    const int4* __restrict__ a4 = (const int4*)attrs;

    const unsigned n_chunks = (unsigned)(n4 / CHUNK_I4);

    // Remainder elements [n_chunks*4096, n): block 0, scalar (usually empty).
    if (blockIdx.x == 0) {
        for (int k = (int)n_chunks * (CHUNK_I4 * 4) + threadIdx.x; k < n;
             k += THREADS_PER_BLOCK)
            acc_elem(preds[k], attrs[k], a0, a1);
    }

    // Dynamic work-stealing: each CTA grabs chunks of 1024 int4.
    if (threadIdx.x == 0) s_chunk[0] = atomicAdd(&g_work, 1u);
    __syncthreads();

    unsigned my = s_chunk[0];
    int buf = 0;
    int pending = 0;
    while (my < n_chunks) {
        buf ^= 1;
        // Prefetch next ticket; its ~318-cyc latency hides under this chunk.
        if (threadIdx.x == 0) s_chunk[buf] = atomicAdd(&g_work, 1u);

        const int base = (int)my * CHUNK_I4 + threadIdx.x;
        // 8 front-batched LDG.128 (4 KB outstanding per warp).
        int4 p0 = p4[base];
        int4 p1 = p4[base + 256];
        int4 p2 = p4[base + 512];
        int4 p3 = p4[base + 768];
        int4 q0 = a4[base];
        int4 q1 = a4[base + 256];
        int4 q2 = a4[base + 512];
        int4 q3 = a4[base + 768];

        acc_elem(p0.x, q0.x, a0, a1);
        acc_elem(p0.y, q0.y, a0, a1);
        acc_elem(p0.z, q0.z, a0, a1);
        acc_elem(p0.w, q0.w, a0, a1);
        acc_elem(p1.x, q1.x, a0, a1);
        acc_elem(p1.y, q1.y, a0, a1);
        acc_elem(p1.z, q1.z, a0, a1);
        acc_elem(p1.w, q1.w, a0, a1);
        acc_elem(p2.x, q2.x, b0, b1);
        acc_elem(p2.y, q2.y, b0, b1);
        acc_elem(p2.z, q2.z, b0, b1);
        acc_elem(p2.w, q2.w, b0, b1);
        acc_elem(p3.x, q3.x, b0, b1);
        acc_elem(p3.y, q3.y, b0, b1);
        acc_elem(p3.z, q3.z, b0, b1);
        acc_elem(p3.w, q3.w, b0, b1);

        // Safety flush: 8 elements/pair/chunk; 15*8 = 120 < 127 capacity.
        if (++pending == 15) {
            flush_pair(a0, a1, blk);
            flush_pair(b0, b1, blk);
            pending = 0;
        }

        __syncthreads();          // next ticket ready; prev slot free
        my = s_chunk[buf];
    }

    flush_pair(a0, a1, blk);
    flush_pair(b0, b1, blk);
    __syncthreads();

    // Block totals -> global atomics
    if (threadIdx.x < N_BINS)
        atomicAdd(&g_counts[threadIdx.x], blk[threadIdx.x]);

    // Release + ticket: last block finalizes. (All of this CTA's g_work
    // atomics happen-before its ticket increment, so the winner may reset.)
    __syncthreads();
    if (threadIdx.x == 0) {
        __threadfence();
        unsigned t = atomicAdd(&g_ticket, 1u);
        is_last = (t == gridDim.x - 1) ? 1u : 0u;
    }
    __syncthreads();

    if (is_last && threadIdx.x == 0) {
        __threadfence();  // acquire side
        float cb[N_BINS];
        #pragma unroll
        for (int c = 0; c < N_BINS; c++)
            cb[c] = (float)atomicAdd(&g_counts[c], 0u);  // coherent read

        float n1 = 0.0f;
        #pragma unroll
        for (int c = 0; c < N_CLASSES; c++) n1 += cb[2 * c + 1];
        float n0 = n_total - n1;

        float s = 0.0f;
        #pragma unroll
        for (int c = 0; c < N_CLASSES; c++) {
            float d = cb[2 * c] / n0 - cb[2 * c + 1] / n1;
            s += d * d;
        }
        out[0] = s;

        // Reset globals for the next graph replay.
        #pragma unroll
        for (int c = 0; c < N_BINS; c++)
            atomicExch(&g_counts[c], 0u);
        atomicExch(&g_work, 0u);
        __threadfence();
        atomicExch(&g_ticket, 0u);
    }
}

extern "C" void kernel_launch(void* const* d_in, const int* in_sizes, int n_in,
                              void* d_out, int out_size)
{
    const int* preds = (const int*)d_in[0];
    const int* attrs = (const int*)d_in[1];
    float* out = (float*)d_out;
    int n  = in_sizes[0];
    int n4 = n >> 2;

    int blocks = NUM_SMS * CTAS_PER_SM;   // one full wave: 592
    int n_chunks = n4 / CHUNK_I4;
    if (blocks > n_chunks && n_chunks > 0) blocks = n_chunks;
    if (blocks < 1) blocks = 1;

    spd_loss_kernel<<<blocks, THREADS_PER_BLOCK>>>(preds, attrs, out, n, n4, (float)n);
}